// round 12
// baseline (speedup 1.0000x reference)
#include <cuda_runtime.h>
#include <cuda_bf16.h>
#include <cstdint>

// MultiDense via mma.sync.m16n8k16 bf16 (sm_80 PTX — no 'a'-feature needed).
// out[i,j,l] = sum_k x[i,j,k]*W[inds[i],l,k] + b[inds[i],l],  I=8192, J=32, K=L=128.
// Split precision: W=Wh+Wl, x=xh+xl (bf16); acc = xh*Wh + xh*Wl + xl*Wh (fp32).
// Warp w: l-range [16w,16w+16) (2 n-tiles), all 32 j (2 m-tiles), K via 8 ksteps.

constexpr int I_TOT   = 8192;
constexpr int F_DIM   = 128;
constexpr int N_NODES = 4096;
constexpr int P_ROW   = 129;
constexpr int P_SZ    = F_DIM * P_ROW;   // 16512 floats/node
constexpr int X_SZ    = 32 * F_DIM;      // 4096 floats/item

constexpr int RSTRIDE = 272;             // padded row stride in bytes (136 bf16); 272%128=16 -> ldmatrix conflict-free
constexpr int SM_BIAS = 0;                       // 128 f32 = 512B
constexpr int SM_WHI  = 512;                     // 128 rows * 272B = 34816
constexpr int SM_WLO  = SM_WHI + 128 * RSTRIDE;  // 34816
constexpr int SM_XHI  = SM_WLO + 128 * RSTRIDE;  // 32 rows * 272 = 8704
constexpr int SM_XLO  = SM_XHI + 32 * RSTRIDE;
constexpr int SMEM_TOTAL = SM_XLO + 32 * RSTRIDE;  // 87552 B

__device__ __forceinline__ unsigned smem_u32(const void* p) {
    unsigned a;
    asm("{.reg .u64 t; cvta.to.shared.u64 t, %1; cvt.u32.u64 %0, t;}" : "=r"(a) : "l"(p));
    return a;
}
__device__ __forceinline__ void ldsm4(unsigned* r, unsigned addr) {
    asm volatile("ldmatrix.sync.aligned.m8n8.x4.shared.b16 {%0,%1,%2,%3}, [%4];"
                 : "=r"(r[0]), "=r"(r[1]), "=r"(r[2]), "=r"(r[3]) : "r"(addr));
}
__device__ __forceinline__ void mma_bf16(float* c, const unsigned* a, const unsigned* b) {
    asm volatile(
        "mma.sync.aligned.m16n8k16.row.col.f32.bf16.bf16.f32 "
        "{%0,%1,%2,%3}, {%4,%5,%6,%7}, {%8,%9}, {%0,%1,%2,%3};"
        : "+f"(c[0]), "+f"(c[1]), "+f"(c[2]), "+f"(c[3])
        : "r"(a[0]), "r"(a[1]), "r"(a[2]), "r"(a[3]), "r"(b[0]), "r"(b[1]));
}
__device__ __forceinline__ void bf_split(float v, unsigned short& h, unsigned short& l) {
    __nv_bfloat16 hb = __float2bfloat16_rn(v);
    __nv_bfloat16 lb = __float2bfloat16_rn(v - __bfloat162float(hb));
    h = __bfloat16_as_ushort(hb);
    l = __bfloat16_as_ushort(lb);
}

__global__ void __launch_bounds__(256, 2)
multidense_mma(const float* __restrict__ x,
               const int* __restrict__ inds,
               const float* __restrict__ params,
               float* __restrict__ out)
{
    extern __shared__ char smem[];
    const unsigned sbase = smem_u32(smem);
    const int tid  = threadIdx.x;
    const int wid  = tid >> 5;
    const int lane = tid & 31;
    const int i    = blockIdx.x;

    int node = inds[i];
    node = min(max(node, 0), N_NODES - 1);
    const float* __restrict__ pblk = params + (size_t)node * P_SZ;

    // ---- stage bias (fp32) ----
    if (tid < 128)
        *reinterpret_cast<float*>(smem + SM_BIAS + tid * 4) = pblk[tid * P_ROW + F_DIM];

    // ---- stage W rows [16*wid, 16*wid+16): per row, lane covers k = 64c + 2*lane, c in {0,1} ----
    #pragma unroll 1
    for (int r = 0; r < 16; ++r) {
        const int l = wid * 16 + r;
        const float* row = pblk + (size_t)l * P_ROW;
        #pragma unroll
        for (int c = 0; c < 2; ++c) {
            const int k0 = 64 * c + 2 * lane;
            const float v0 = row[k0], v1 = row[k0 + 1];
            unsigned short h0, l0b, h1, l1b;
            bf_split(v0, h0, l0b);
            bf_split(v1, h1, l1b);
            const int off = l * RSTRIDE + 128 * c + 4 * lane;  // (64c+2lane)*2 bytes
            *reinterpret_cast<unsigned*>(smem + SM_WHI + off) = ((unsigned)h1 << 16) | h0;
            *reinterpret_cast<unsigned*>(smem + SM_WLO + off) = ((unsigned)l1b << 16) | l0b;
        }
    }

    // ---- stage x rows [4*wid, 4*wid+4): lane covers k = 4*lane..4*lane+3 (float4) ----
    #pragma unroll
    for (int r = 0; r < 4; ++r) {
        const int j = wid * 4 + r;
        const float4 v = *reinterpret_cast<const float4*>(
            x + (size_t)i * X_SZ + (size_t)j * F_DIM + 4 * lane);
        unsigned short h0, a0, h1, a1, h2, a2, h3, a3;
        bf_split(v.x, h0, a0);
        bf_split(v.y, h1, a1);
        bf_split(v.z, h2, a2);
        bf_split(v.w, h3, a3);
        const int off = j * RSTRIDE + 8 * lane;
        unsigned hp0 = ((unsigned)h1 << 16) | h0, hp1 = ((unsigned)h3 << 16) | h2;
        unsigned lp0 = ((unsigned)a1 << 16) | a0, lp1 = ((unsigned)a3 << 16) | a2;
        *reinterpret_cast<uint2*>(smem + SM_XHI + off) = make_uint2(hp0, hp1);
        *reinterpret_cast<uint2*>(smem + SM_XLO + off) = make_uint2(lp0, lp1);
    }
    __syncthreads();

    // ---- k-loop: warp computes 32j x 16l; acc[mt][nt][4] ----
    const int l0 = wid * 16;

    // ldmatrix per-lane address offsets
    // A (x, m16k16): matrices (r0-7,k0),(r8-15,k0),(r0-7,k8),(r8-15,k8): row = lane&15, kblk16B = lane>>4
    const int a_off = (lane & 15) * RSTRIDE + (lane >> 4) * 16;
    // B (W, n16k16 as 4 8x8): (l0..+7,k0),(l0..+7,k8),(l0+8..,k0),(l0+8..,k8):
    // row = (lane&7) + (lane>>4)*8, kblk16B = (lane>>3)&1
    const int b_off = ((lane & 7) + ((lane >> 4) & 1) * 8 + l0) * RSTRIDE + ((lane >> 3) & 1) * 16;

    float acc[2][2][4];
    #pragma unroll
    for (int mt = 0; mt < 2; ++mt)
        #pragma unroll
        for (int nt = 0; nt < 2; ++nt)
            #pragma unroll
            for (int q = 0; q < 4; ++q) acc[mt][nt][q] = 0.0f;

    #pragma unroll
    for (int ks = 0; ks < 8; ++ks) {
        const int kb = ks * 32;   // 16 bf16 = 32 bytes per kstep
        unsigned aHi[2][4], aLo[2][4], bHi[4], bLo[4];
        #pragma unroll
        for (int mt = 0; mt < 2; ++mt) {
            ldsm4(aHi[mt], sbase + SM_XHI + mt * 16 * RSTRIDE + a_off + kb);
            ldsm4(aLo[mt], sbase + SM_XLO + mt * 16 * RSTRIDE + a_off + kb);
        }
        ldsm4(bHi, sbase + SM_WHI + b_off + kb);
        ldsm4(bLo, sbase + SM_WLO + b_off + kb);

        #pragma unroll
        for (int mt = 0; mt < 2; ++mt)
            #pragma unroll
            for (int nt = 0; nt < 2; ++nt) {
                mma_bf16(acc[mt][nt], aHi[mt], bHi + nt * 2);
                mma_bf16(acc[mt][nt], aHi[mt], bLo + nt * 2);
                mma_bf16(acc[mt][nt], aLo[mt], bHi + nt * 2);
            }
    }

    // ---- epilogue: add bias, store. C frag: row j = mt*16 + (lane>>2) (+8 for c2/c3),
    //      col l = l0 + nt*8 + 2*(lane&3) (+1) ----
    float* o = out + (size_t)i * X_SZ;
    #pragma unroll
    for (int nt = 0; nt < 2; ++nt) {
        const int l = l0 + nt * 8 + 2 * (lane & 3);
        const float2 bv = *reinterpret_cast<const float2*>(smem + SM_BIAS + l * 4);
        #pragma unroll
        for (int mt = 0; mt < 2; ++mt) {
            const int j = mt * 16 + (lane >> 2);
            float2 r0 = make_float2(acc[mt][nt][0] + bv.x, acc[mt][nt][1] + bv.y);
            float2 r1 = make_float2(acc[mt][nt][2] + bv.x, acc[mt][nt][3] + bv.y);
            *reinterpret_cast<float2*>(o + (size_t)j * F_DIM + l) = r0;
            *reinterpret_cast<float2*>(o + (size_t)(j + 8) * F_DIM + l) = r1;
        }
    }
}

extern "C" void kernel_launch(void* const* d_in, const int* in_sizes, int n_in,
                              void* d_out, int out_size)
{
    const float* x      = (const float*)d_in[0];   // [8192,32,128] f32
    const int*   inds   = (const int*)d_in[1];     // [8192] int32
    const float* params = (const float*)d_in[2];   // [4096,128,129] f32
    float*       out    = (float*)d_out;           // [8192,32,128] f32

    (void)in_sizes; (void)n_in; (void)out_size;

    cudaFuncSetAttribute(multidense_mma,
                         cudaFuncAttributeMaxDynamicSharedMemorySize, SMEM_TOTAL);

    multidense_mma<<<I_TOT, 256, SMEM_TOTAL>>>(x, inds, params, out);
}

// round 13
// speedup vs baseline: 1.3975x; 1.3975x over previous
#include <cuda_runtime.h>
#include <cuda_bf16.h>
#include <cstdint>

// MultiDense via mma.sync.m16n8k16 bf16, split-L: 2 CTAs per item (64 l each).
// out[i,j,l] = sum_k x[i,j,k]*W[inds[i],l,k] + b[inds[i],l],  I=8192, J=32, K=L=128.
// Split precision: W=Wh+Wl, x=xh+xl (bf16); acc = xh*Wh + xh*Wl + xl*Wh (fp32).
// CTA (i, h): l in [64h, 64h+64). Warp w: l-tile [8w,8w+8) local, all 32 j.
// smem 52.7KB -> 4 CTAs/SM (vs 2) to hide the gather/stage latency chain.

constexpr int I_TOT   = 8192;
constexpr int F_DIM   = 128;
constexpr int N_NODES = 4096;
constexpr int P_ROW   = 129;
constexpr int P_SZ    = F_DIM * P_ROW;   // 16512 floats/node
constexpr int X_SZ    = 32 * F_DIM;      // 4096 floats/item
constexpr int L_HALF  = 64;

constexpr int RSTRIDE = 272;             // padded row stride bytes (136 bf16): ldmatrix conflict-free
constexpr int SM_BIAS = 0;                        // 64 f32 = 256B (pad to 512)
constexpr int SM_WHI  = 512;                      // 64 rows * 272B = 17408
constexpr int SM_WLO  = SM_WHI + 64 * RSTRIDE;    // 17920
constexpr int SM_XHI  = SM_WLO + 64 * RSTRIDE;    // 35328
constexpr int SM_XLO  = SM_XHI + 32 * RSTRIDE;    // 44032
constexpr int SMEM_TOTAL = SM_XLO + 32 * RSTRIDE; // 52736 B -> 4 CTAs/SM

__device__ __forceinline__ unsigned smem_u32(const void* p) {
    unsigned a;
    asm("{.reg .u64 t; cvta.to.shared.u64 t, %1; cvt.u32.u64 %0, t;}" : "=r"(a) : "l"(p));
    return a;
}
__device__ __forceinline__ void ldsm4(unsigned* r, unsigned addr) {
    asm volatile("ldmatrix.sync.aligned.m8n8.x4.shared.b16 {%0,%1,%2,%3}, [%4];"
                 : "=r"(r[0]), "=r"(r[1]), "=r"(r[2]), "=r"(r[3]) : "r"(addr));
}
__device__ __forceinline__ void ldsm2(unsigned* r, unsigned addr) {
    asm volatile("ldmatrix.sync.aligned.m8n8.x2.shared.b16 {%0,%1}, [%2];"
                 : "=r"(r[0]), "=r"(r[1]) : "r"(addr));
}
__device__ __forceinline__ void mma_bf16(float* c, const unsigned* a, const unsigned* b) {
    asm volatile(
        "mma.sync.aligned.m16n8k16.row.col.f32.bf16.bf16.f32 "
        "{%0,%1,%2,%3}, {%4,%5,%6,%7}, {%8,%9}, {%0,%1,%2,%3};"
        : "+f"(c[0]), "+f"(c[1]), "+f"(c[2]), "+f"(c[3])
        : "r"(a[0]), "r"(a[1]), "r"(a[2]), "r"(a[3]), "r"(b[0]), "r"(b[1]));
}
__device__ __forceinline__ void bf_split(float v, unsigned short& h, unsigned short& l) {
    __nv_bfloat16 hb = __float2bfloat16_rn(v);
    __nv_bfloat16 lb = __float2bfloat16_rn(v - __bfloat162float(hb));
    h = __bfloat16_as_ushort(hb);
    l = __bfloat16_as_ushort(lb);
}

__global__ void __launch_bounds__(256, 4)
multidense_mma(const float* __restrict__ x,
               const int* __restrict__ inds,
               const float* __restrict__ params,
               float* __restrict__ out)
{
    extern __shared__ char smem[];
    const unsigned sbase = smem_u32(smem);
    const int tid  = threadIdx.x;
    const int wid  = tid >> 5;
    const int lane = tid & 31;
    const int i    = blockIdx.x >> 1;     // item
    const int h    = blockIdx.x & 1;      // l-half

    int node = inds[i];
    node = min(max(node, 0), N_NODES - 1);
    const float* __restrict__ pblk = params + (size_t)node * P_SZ;

    // ---- stage bias (64 f32 for this half) ----
    if (tid < L_HALF)
        *reinterpret_cast<float*>(smem + SM_BIAS + tid * 4) =
            pblk[(size_t)(h * L_HALF + tid) * P_ROW + F_DIM];

    // ---- stage W rows: warp w -> local rows [8w, 8w+8); lane covers k = 64c + 2*lane ----
    #pragma unroll 1
    for (int r = 0; r < 8; ++r) {
        const int lr = wid * 8 + r;                    // local row in tile
        const float* row = pblk + (size_t)(h * L_HALF + lr) * P_ROW;
        #pragma unroll
        for (int c = 0; c < 2; ++c) {
            const int k0 = 64 * c + 2 * lane;
            const float v0 = row[k0], v1 = row[k0 + 1];
            unsigned short h0, l0b, h1, l1b;
            bf_split(v0, h0, l0b);
            bf_split(v1, h1, l1b);
            const int off = lr * RSTRIDE + 128 * c + 4 * lane;
            *reinterpret_cast<unsigned*>(smem + SM_WHI + off) = ((unsigned)h1 << 16) | h0;
            *reinterpret_cast<unsigned*>(smem + SM_WLO + off) = ((unsigned)l1b << 16) | l0b;
        }
    }

    // ---- stage x rows [4*wid, 4*wid+4): lane covers k = 4*lane..+3 (float4) ----
    #pragma unroll
    for (int r = 0; r < 4; ++r) {
        const int j = wid * 4 + r;
        const float4 v = *reinterpret_cast<const float4*>(
            x + (size_t)i * X_SZ + (size_t)j * F_DIM + 4 * lane);
        unsigned short h0, a0, h1, a1, h2, a2, h3, a3;
        bf_split(v.x, h0, a0);
        bf_split(v.y, h1, a1);
        bf_split(v.z, h2, a2);
        bf_split(v.w, h3, a3);
        const int off = j * RSTRIDE + 8 * lane;
        unsigned hp0 = ((unsigned)h1 << 16) | h0, hp1 = ((unsigned)h3 << 16) | h2;
        unsigned lp0 = ((unsigned)a1 << 16) | a0, lp1 = ((unsigned)a3 << 16) | a2;
        *reinterpret_cast<uint2*>(smem + SM_XHI + off) = make_uint2(hp0, hp1);
        *reinterpret_cast<uint2*>(smem + SM_XLO + off) = make_uint2(lp0, lp1);
    }
    __syncthreads();

    // ---- k-loop: warp computes 32 j x 8 l (local l-tile base = 8*wid) ----
    const int l0 = wid * 8;

    // A (x, m16k16): row = lane&15, kblk16B = lane>>4
    const int a_off = (lane & 15) * RSTRIDE + (lane >> 4) * 16;
    // B (W, n8k16 via x2): row = l0 + (lane&7), kblk16B = (lane>>3)&1
    const int b_off = (l0 + (lane & 7)) * RSTRIDE + ((lane >> 3) & 1) * 16;

    float acc[2][4];
    #pragma unroll
    for (int mt = 0; mt < 2; ++mt)
        #pragma unroll
        for (int q = 0; q < 4; ++q) acc[mt][q] = 0.0f;

    #pragma unroll
    for (int ks = 0; ks < 8; ++ks) {
        const int kb = ks * 32;
        unsigned aHi[2][4], aLo[2][4], bHi[2], bLo[2];
        #pragma unroll
        for (int mt = 0; mt < 2; ++mt) {
            ldsm4(aHi[mt], sbase + SM_XHI + mt * 16 * RSTRIDE + a_off + kb);
            ldsm4(aLo[mt], sbase + SM_XLO + mt * 16 * RSTRIDE + a_off + kb);
        }
        ldsm2(bHi, sbase + SM_WHI + b_off + kb);
        ldsm2(bLo, sbase + SM_WLO + b_off + kb);

        #pragma unroll
        for (int mt = 0; mt < 2; ++mt) {
            mma_bf16(acc[mt], aHi[mt], bHi);
            mma_bf16(acc[mt], aHi[mt], bLo);
            mma_bf16(acc[mt], aLo[mt], bHi);
        }
    }

    // ---- epilogue: C frag row j = mt*16 + (lane>>2) (+8), col l = l0 + 2*(lane&3) (+1) ----
    float* o = out + (size_t)i * X_SZ;
    const int lc = l0 + 2 * (lane & 3);                // local l
    const int lg = h * L_HALF + lc;                    // global l
    const float2 bv = *reinterpret_cast<const float2*>(smem + SM_BIAS + lc * 4);
    #pragma unroll
    for (int mt = 0; mt < 2; ++mt) {
        const int j = mt * 16 + (lane >> 2);
        float2 r0 = make_float2(acc[mt][0] + bv.x, acc[mt][1] + bv.y);
        float2 r1 = make_float2(acc[mt][2] + bv.x, acc[mt][3] + bv.y);
        *reinterpret_cast<float2*>(o + (size_t)j * F_DIM + lg) = r0;
        *reinterpret_cast<float2*>(o + (size_t)(j + 8) * F_DIM + lg) = r1;
    }
}

extern "C" void kernel_launch(void* const* d_in, const int* in_sizes, int n_in,
                              void* d_out, int out_size)
{
    const float* x      = (const float*)d_in[0];   // [8192,32,128] f32
    const int*   inds   = (const int*)d_in[1];     // [8192] int32
    const float* params = (const float*)d_in[2];   // [4096,128,129] f32
    float*       out    = (float*)d_out;           // [8192,32,128] f32

    (void)in_sizes; (void)n_in; (void)out_size;

    cudaFuncSetAttribute(multidense_mma,
                         cudaFuncAttributeMaxDynamicSharedMemorySize, SMEM_TOTAL);

    multidense_mma<<<I_TOT * 2, 256, SMEM_TOTAL>>>(x, inds, params, out);
}

// round 16
// speedup vs baseline: 1.4237x; 1.0188x over previous
#include <cuda_runtime.h>
#include <cuda_bf16.h>
#include <cstdint>

// MultiDense via mma.sync.m16n8k16 bf16, split-L: 2 CTAs per item (64 l each).
// Warp partition: 8 warps = 2 m-tiles x 4 l-groups of 16 l.
// W gather: SCALAR loads only — param rows have stride 129 floats = 516B == 4 mod 8,
// so odd rows are not 8B-aligned (float2 gather traps: R14 post-mortem).
// Split precision: W=Wh+Wl, x=xh+xl (bf16); acc = xh*Wh + xh*Wl + xl*Wh (fp32 acc).

constexpr int I_TOT   = 8192;
constexpr int F_DIM   = 128;
constexpr int N_NODES = 4096;
constexpr int P_ROW   = 129;
constexpr int P_SZ    = F_DIM * P_ROW;   // 16512 floats/node
constexpr int X_SZ    = 32 * F_DIM;      // 4096 floats/item
constexpr int L_HALF  = 64;

constexpr int RSTRIDE = 272;             // padded row stride bytes: ldmatrix conflict-free
constexpr int SM_BIAS = 0;                        // 64 f32 (pad 512)
constexpr int SM_WHI  = 512;                      // 64 rows * 272B
constexpr int SM_WLO  = SM_WHI + 64 * RSTRIDE;
constexpr int SM_XHI  = SM_WLO + 64 * RSTRIDE;    // 32 rows * 272B
constexpr int SM_XLO  = SM_XHI + 32 * RSTRIDE;
constexpr int SMEM_TOTAL = SM_XLO + 32 * RSTRIDE; // 52736 B -> 4 CTAs/SM

__device__ __forceinline__ unsigned smem_u32(const void* p) {
    unsigned a;
    asm("{.reg .u64 t; cvta.to.shared.u64 t, %1; cvt.u32.u64 %0, t;}" : "=r"(a) : "l"(p));
    return a;
}
__device__ __forceinline__ void ldsm4(unsigned* r, unsigned addr) {
    asm volatile("ldmatrix.sync.aligned.m8n8.x4.shared.b16 {%0,%1,%2,%3}, [%4];"
                 : "=r"(r[0]), "=r"(r[1]), "=r"(r[2]), "=r"(r[3]) : "r"(addr));
}
__device__ __forceinline__ void mma_bf16(float* c, const unsigned* a, const unsigned* b) {
    asm volatile(
        "mma.sync.aligned.m16n8k16.row.col.f32.bf16.bf16.f32 "
        "{%0,%1,%2,%3}, {%4,%5,%6,%7}, {%8,%9}, {%0,%1,%2,%3};"
        : "+f"(c[0]), "+f"(c[1]), "+f"(c[2]), "+f"(c[3])
        : "r"(a[0]), "r"(a[1]), "r"(a[2]), "r"(a[3]), "r"(b[0]), "r"(b[1]));
}
__device__ __forceinline__ void bf_split(float v, unsigned short& h, unsigned short& l) {
    __nv_bfloat16 hb = __float2bfloat16_rn(v);
    __nv_bfloat16 lb = __float2bfloat16_rn(v - __bfloat162float(hb));
    h = __bfloat16_as_ushort(hb);
    l = __bfloat16_as_ushort(lb);
}

__global__ void __launch_bounds__(256, 4)
multidense_mma(const float* __restrict__ x,
               const int* __restrict__ inds,
               const float* __restrict__ params,
               float* __restrict__ out)
{
    extern __shared__ char smem[];
    const unsigned sbase = smem_u32(smem);
    const int tid  = threadIdx.x;
    const int wid  = tid >> 5;
    const int lane = tid & 31;
    const int i    = blockIdx.x >> 1;     // item
    const int h    = blockIdx.x & 1;      // l-half

    int node = inds[i];
    node = min(max(node, 0), N_NODES - 1);
    const float* __restrict__ pblk = params + (size_t)node * P_SZ;

    // ---- stage bias ----
    if (tid < L_HALF)
        *reinterpret_cast<float*>(smem + SM_BIAS + tid * 4) =
            pblk[(size_t)(h * L_HALF + tid) * P_ROW + F_DIM];

    // ---- stage W rows: warp w -> local rows [8w, 8w+8); SCALAR loads (stride-129 rows) ----
    #pragma unroll 1
    for (int r = 0; r < 8; ++r) {
        const int lr = wid * 8 + r;
        const float* row = pblk + (size_t)(h * L_HALF + lr) * P_ROW;
        #pragma unroll
        for (int c = 0; c < 2; ++c) {
            const int k0 = 64 * c + 2 * lane;
            const float v0 = row[k0];
            const float v1 = row[k0 + 1];
            unsigned short h0, l0b, h1, l1b;
            bf_split(v0, h0, l0b);
            bf_split(v1, h1, l1b);
            const int off = lr * RSTRIDE + 128 * c + 4 * lane;
            *reinterpret_cast<unsigned*>(smem + SM_WHI + off) = ((unsigned)h1 << 16) | h0;
            *reinterpret_cast<unsigned*>(smem + SM_WLO + off) = ((unsigned)l1b << 16) | l0b;
        }
    }

    // ---- stage x rows [4*wid, 4*wid+4): float4 gather (x rows are 512B stride, aligned) ----
    #pragma unroll
    for (int r = 0; r < 4; ++r) {
        const int j = wid * 4 + r;
        const float4 v = *reinterpret_cast<const float4*>(
            x + (size_t)i * X_SZ + (size_t)j * F_DIM + 4 * lane);
        unsigned short h0, a0, h1, a1, h2, a2, h3, a3;
        bf_split(v.x, h0, a0);
        bf_split(v.y, h1, a1);
        bf_split(v.z, h2, a2);
        bf_split(v.w, h3, a3);
        const int off = j * RSTRIDE + 8 * lane;
        unsigned hp0 = ((unsigned)h1 << 16) | h0, hp1 = ((unsigned)h3 << 16) | h2;
        unsigned lp0 = ((unsigned)a1 << 16) | a0, lp1 = ((unsigned)a3 << 16) | a2;
        *reinterpret_cast<uint2*>(smem + SM_XHI + off) = make_uint2(hp0, hp1);
        *reinterpret_cast<uint2*>(smem + SM_XLO + off) = make_uint2(lp0, lp1);
    }
    __syncthreads();

    // ---- warp partition: mt = wid & 1 (j-tile), l-group = wid >> 1 (16 l each) ----
    const int mt = wid & 1;
    const int l0 = (wid >> 1) * 16;       // local l base

    // A (x tile rows [16mt,16mt+16)): row = lane&15, kblk16B = lane>>4
    const int a_off = (mt * 16 + (lane & 15)) * RSTRIDE + (lane >> 4) * 16;
    // B (W, n16k16 x4): row = l0 + (lane&7) + ((lane>>4)&1)*8, kblk16B = (lane>>3)&1
    const int b_off = (l0 + (lane & 7) + ((lane >> 4) & 1) * 8) * RSTRIDE
                      + ((lane >> 3) & 1) * 16;

    float acc[2][4];   // [nt][quad]
    #pragma unroll
    for (int nt = 0; nt < 2; ++nt)
        #pragma unroll
        for (int q = 0; q < 4; ++q) acc[nt][q] = 0.0f;

    #pragma unroll
    for (int ks = 0; ks < 8; ++ks) {
        const int kb = ks * 32;
        unsigned aHi[4], aLo[4], bHi[4], bLo[4];
        ldsm4(aHi, sbase + SM_XHI + a_off + kb);
        ldsm4(aLo, sbase + SM_XLO + a_off + kb);
        ldsm4(bHi, sbase + SM_WHI + b_off + kb);
        ldsm4(bLo, sbase + SM_WLO + b_off + kb);

        #pragma unroll
        for (int nt = 0; nt < 2; ++nt) {
            mma_bf16(acc[nt], aHi, bHi + nt * 2);
            mma_bf16(acc[nt], aHi, bLo + nt * 2);
            mma_bf16(acc[nt], aLo, bHi + nt * 2);
        }
    }

    // ---- epilogue: C frag row j = mt*16 + (lane>>2) (+8), col l = l0 + nt*8 + 2*(lane&3) ----
    float* o = out + (size_t)i * X_SZ;
    #pragma unroll
    for (int nt = 0; nt < 2; ++nt) {
        const int lc = l0 + nt * 8 + 2 * (lane & 3);   // local l (even -> bias float2 aligned)
        const int lg = h * L_HALF + lc;                // global l
        const float2 bv = *reinterpret_cast<const float2*>(smem + SM_BIAS + lc * 4);
        const int j = mt * 16 + (lane >> 2);
        float2 r0 = make_float2(acc[nt][0] + bv.x, acc[nt][1] + bv.y);
        float2 r1 = make_float2(acc[nt][2] + bv.x, acc[nt][3] + bv.y);
        *reinterpret_cast<float2*>(o + (size_t)j * F_DIM + lg) = r0;
        *reinterpret_cast<float2*>(o + (size_t)(j + 8) * F_DIM + lg) = r1;
    }
}

extern "C" void kernel_launch(void* const* d_in, const int* in_sizes, int n_in,
                              void* d_out, int out_size)
{
    const float* x      = (const float*)d_in[0];   // [8192,32,128] f32
    const int*   inds   = (const int*)d_in[1];     // [8192] int32
    const float* params = (const float*)d_in[2];   // [4096,128,129] f32
    float*       out    = (float*)d_out;           // [8192,32,128] f32

    (void)in_sizes; (void)n_in; (void)out_size;

    cudaFuncSetAttribute(multidense_mma,
                         cudaFuncAttributeMaxDynamicSharedMemorySize, SMEM_TOTAL);

    multidense_mma<<<I_TOT * 2, 256, SMEM_TOTAL>>>(x, inds, params, out);
}